// round 4
// baseline (speedup 1.0000x reference)
#include <cuda_runtime.h>
#include <math.h>

// ---------------- problem constants ----------------
#define NB   128
#define CCH  256
#define MH_  28
#define MW_  28
#define HW_  784
#define KCLS 80
#define PP   196
#define SH__ 200
#define SW__ 200
#define SPIX 40000          // 200*200
#define FCIN 416            // C + 2K
#define NCOL (NB*PP)        // 25088 point-columns
#define NPIX (NB*HW_)       // 100352 instance pixels

// ---------------- scratch (static device globals; no allocation) ----------------
__device__ float g_semFT[SPIX*CCH];            // semantic feat, pixel-major [pix][c]
__device__ float g_semT [SPIX*CCH];            // relu(sem conv), pixel-major [pix][o]
__device__ float g_Ft [(size_t)NPIX*CCH];      // instance feats, pixel-major [n*784+pix][c]
__device__ float g_X0 [(size_t)NCOL*FCIN];     // MLP ping buffer [col][416]
__device__ float g_X1 [(size_t)NCOL*FCIN];     // MLP pong buffer [col][416]
__device__ float g_G  [(size_t)NCOL*CCH];      // gathered inst feats at points [col][c]
__device__ float g_P  [(size_t)NCOL*CCH];      // point logits [col][c]
__device__ float g_R  [(size_t)NPIX*CCH];      // refined feats [n*784+pix][c]
__device__ float g_F  [(size_t)CCH*NPIX];      // fused, channel-major [c][n*784+pix]
__device__ int   g_idx[NB*PP];                 // selected point indices
__device__ float g_Wid[160*CCH];               // stacked [w_inst; w_det]
__device__ float g_Bid[160];

// ---------------- generic TN SGEMM: C = op(A[M,K] @ B^T + bias) ----------------
// A row-major [M][K]. B stored as [col][K] (ldb). Ncol % 64 == 0, K % 16 == 0.
// STORE_T: C[col*ldc + row]  else C[row*ldc + col].
template<bool STORE_T, bool RELU>
__global__ void gemm_k(const float* __restrict__ A, const float* __restrict__ B,
                       float* __restrict__ C, const float* __restrict__ bias,
                       int M, int Kd, int ldb, int ldc)
{
    __shared__ float As[16][64];
    __shared__ float Bs[16][64];
    const int t  = threadIdx.x;
    const int tx = t & 15, ty = t >> 4;
    const int rowTile = blockIdx.y * 64;
    const int colTile = blockIdx.x * 64;
    const int lr = t >> 2;          // 0..63
    const int lk = (t & 3) * 4;     // 0,4,8,12
    float acc[4][4];
    #pragma unroll
    for (int i = 0; i < 4; i++)
        #pragma unroll
        for (int j = 0; j < 4; j++) acc[i][j] = 0.f;

    for (int k0 = 0; k0 < Kd; k0 += 16) {
        int ar = rowTile + lr;
        float4 av = make_float4(0.f,0.f,0.f,0.f);
        if (ar < M) av = *reinterpret_cast<const float4*>(A + (size_t)ar*Kd + k0 + lk);
        As[lk+0][lr]=av.x; As[lk+1][lr]=av.y; As[lk+2][lr]=av.z; As[lk+3][lr]=av.w;
        float4 bv = *reinterpret_cast<const float4*>(B + (size_t)(colTile+lr)*ldb + k0 + lk);
        Bs[lk+0][lr]=bv.x; Bs[lk+1][lr]=bv.y; Bs[lk+2][lr]=bv.z; Bs[lk+3][lr]=bv.w;
        __syncthreads();
        #pragma unroll
        for (int kk = 0; kk < 16; kk++) {
            float4 a = *reinterpret_cast<const float4*>(&As[kk][ty*4]);
            float4 b = *reinterpret_cast<const float4*>(&Bs[kk][tx*4]);
            acc[0][0] = fmaf(a.x,b.x,acc[0][0]); acc[0][1] = fmaf(a.x,b.y,acc[0][1]);
            acc[0][2] = fmaf(a.x,b.z,acc[0][2]); acc[0][3] = fmaf(a.x,b.w,acc[0][3]);
            acc[1][0] = fmaf(a.y,b.x,acc[1][0]); acc[1][1] = fmaf(a.y,b.y,acc[1][1]);
            acc[1][2] = fmaf(a.y,b.z,acc[1][2]); acc[1][3] = fmaf(a.y,b.w,acc[1][3]);
            acc[2][0] = fmaf(a.z,b.x,acc[2][0]); acc[2][1] = fmaf(a.z,b.y,acc[2][1]);
            acc[2][2] = fmaf(a.z,b.z,acc[2][2]); acc[2][3] = fmaf(a.z,b.w,acc[2][3]);
            acc[3][0] = fmaf(a.w,b.x,acc[3][0]); acc[3][1] = fmaf(a.w,b.y,acc[3][1]);
            acc[3][2] = fmaf(a.w,b.z,acc[3][2]); acc[3][3] = fmaf(a.w,b.w,acc[3][3]);
        }
        __syncthreads();
    }

    const int m0 = rowTile + ty*4, c0 = colTile + tx*4;
    #pragma unroll
    for (int i = 0; i < 4; i++) {
        float bv = ((m0+i) < M) ? bias[m0+i] : 0.f;
        #pragma unroll
        for (int j = 0; j < 4; j++) {
            float v = acc[i][j] + bv;
            if (RELU) v = fmaxf(v, 0.f);
            acc[i][j] = v;
        }
    }
    if (STORE_T) {
        if (m0 + 3 < M) {
            #pragma unroll
            for (int j = 0; j < 4; j++) {
                float4 v = make_float4(acc[0][j],acc[1][j],acc[2][j],acc[3][j]);
                *reinterpret_cast<float4*>(C + (size_t)(c0+j)*ldc + m0) = v;
            }
        } else {
            for (int j = 0; j < 4; j++)
                for (int i = 0; i < 4; i++)
                    if (m0+i < M) C[(size_t)(c0+j)*ldc + m0+i] = acc[i][j];
        }
    } else {
        #pragma unroll
        for (int i = 0; i < 4; i++)
            if (m0+i < M)
                *reinterpret_cast<float4*>(C + (size_t)(m0+i)*ldc + c0)
                    = make_float4(acc[i][0],acc[i][1],acc[i][2],acc[i][3]);
    }
}

// ---------------- batched 2D transpose [b][R][Cc] -> [b][Cc][R] ----------------
__global__ void transpose_k(const float* __restrict__ in, float* __restrict__ out,
                            int R, int Cc)
{
    __shared__ float tile[32][33];
    const int b = blockIdx.z;
    const float* ip = in  + (size_t)b*R*Cc;
    float*       op = out + (size_t)b*R*Cc;
    int x = blockIdx.x*32 + threadIdx.x;
    #pragma unroll
    for (int j = 0; j < 32; j += 8) {
        int y = blockIdx.y*32 + threadIdx.y + j;
        if (y < R && x < Cc) tile[threadIdx.y+j][threadIdx.x] = ip[(size_t)y*Cc + x];
    }
    __syncthreads();
    int x2 = blockIdx.y*32 + threadIdx.x;
    #pragma unroll
    for (int j = 0; j < 32; j += 8) {
        int y2 = blockIdx.x*32 + threadIdx.y + j;
        if (y2 < Cc && x2 < R) op[(size_t)y2*R + x2] = tile[threadIdx.x][threadIdx.y+j];
    }
}

// ---------------- stack class weights ----------------
__global__ void wid_k(const float* __restrict__ wi, const float* __restrict__ bi,
                      const float* __restrict__ wd, const float* __restrict__ bd)
{
    for (int i = threadIdx.x; i < 160*CCH; i += blockDim.x) {
        int r = i >> 8, c = i & 255;
        g_Wid[i] = (r < KCLS) ? wi[r*CCH + c] : wd[(r-KCLS)*CCH + c];
    }
    for (int i = threadIdx.x; i < 160; i += blockDim.x)
        g_Bid[i] = (i < KCLS) ? bi[i] : bd[i-KCLS];
}

// ---------------- per-ROI label-selected maps (instance_preds / detail_preds) ----------------
__global__ void class_select_k(const float* __restrict__ w_inst, const float* __restrict__ b_inst,
                               const float* __restrict__ w_det,  const float* __restrict__ b_det,
                               const int* __restrict__ labels, float* __restrict__ out)
{
    __shared__ float swi[CCH], swd[CCH];
    const int n = blockIdx.x;
    const int lab = labels[n];
    const int t = threadIdx.x;
    if (t < CCH) { swi[t] = w_inst[lab*CCH + t]; swd[t] = w_det[lab*CCH + t]; }
    __syncthreads();
    const float bi = b_inst[lab], bd = b_det[lab];
    const int lane = t & 31, w = t >> 5;
    for (int p = w; p < HW_; p += 8) {
        const float* f = g_Ft + ((size_t)n*HW_ + p)*CCH;
        float si = 0.f, sd = 0.f;
        for (int c = lane; c < CCH; c += 32) {
            float v = f[c];
            si = fmaf(v, swi[c], si);
            sd = fmaf(v, swd[c], sd);
        }
        #pragma unroll
        for (int o = 16; o; o >>= 1) {
            si += __shfl_down_sync(0xffffffffu, si, o);
            sd += __shfl_down_sync(0xffffffffu, sd, o);
        }
        if (lane == 0) {
            out[n*HW_ + p]        = si + bi;   // instance_preds
            out[NPIX + n*HW_ + p] = sd + bd;   // detail_preds
        }
    }
}

// ---------------- top-196 of 784 per ROI (bitonic; order inside P is irrelevant) ----------------
__global__ void topk_k(const float* __restrict__ det)
{
    __shared__ float sv[1024];
    __shared__ int   si[1024];
    const int n = blockIdx.x, t = threadIdx.x;
    for (int i = t; i < 1024; i += 512) {
        sv[i] = (i < HW_) ? det[NPIX + n*HW_ + i] : -3.4e38f;
        si[i] = i;
    }
    __syncthreads();
    for (int k2 = 2; k2 <= 1024; k2 <<= 1)
        for (int j = k2 >> 1; j > 0; j >>= 1) {
            int i = 2*t - (t & (j-1));
            int r = i + j;
            bool desc = ((i & k2) == 0);
            float vl = sv[i], vr = sv[r];
            bool sw = desc ? (vl < vr) : (vl > vr);
            if (sw) {
                sv[i] = vr; sv[r] = vl;
                int tmp = si[i]; si[i] = si[r]; si[r] = tmp;
            }
            __syncthreads();
        }
    if (t < PP) g_idx[n*PP + t] = si[t];
}

// ---------------- per-point: bilinear 'fine' + instance feat gather ----------------
__global__ void gather_k(const float* __restrict__ rois)
{
    const int col = blockIdx.x;           // n*PP + p
    const int n = col / PP;
    const int c = threadIdx.x;            // 256 threads = channels
    const int pix = g_idx[col];
    const float x1 = __ldg(rois + n*5 + 1), y1 = __ldg(rois + n*5 + 2);
    const float x2 = __ldg(rois + n*5 + 3), y2 = __ldg(rois + n*5 + 4);
    const float relx = ((pix % MW_) + 0.5f) / (float)MW_;
    const float rely = ((pix / MW_) + 0.5f) / (float)MH_;
    const float px = (x1 + relx*(x2 - x1)) * 0.25f - 0.5f;
    const float py = (y1 + rely*(y2 - y1)) * 0.25f - 0.5f;
    const float x0f = floorf(px), y0f = floorf(py);
    const float wx = px - x0f, wy = py - y0f;
    const int ix0 = (int)x0f, iy0 = (int)y0f;
    const int x0c = min(max(ix0, 0), SW__-1),   x1c = min(max(ix0+1, 0), SW__-1);
    const int y0c = min(max(iy0, 0), SH__-1),   y1c = min(max(iy0+1, 0), SH__-1);
    const float vx0 = (ix0   >= 0 && ix0   < SW__) ? 1.f : 0.f;
    const float vx1 = (ix0+1 >= 0 && ix0+1 < SW__) ? 1.f : 0.f;
    const float vy0 = (iy0   >= 0 && iy0   < SH__) ? 1.f : 0.f;
    const float vy1 = (iy0+1 >= 0 && iy0+1 < SH__) ? 1.f : 0.f;
    const float w00 = (1.f-wx)*(1.f-wy)*vx0*vy0;
    const float w10 = wx*(1.f-wy)*vx1*vy0;
    const float w01 = (1.f-wx)*wy*vx0*vy1;
    const float w11 = wx*wy*vx1*vy1;
    float v = w00 * g_semT[(size_t)(y0c*SW__ + x0c)*CCH + c]
            + w10 * g_semT[(size_t)(y0c*SW__ + x1c)*CCH + c]
            + w01 * g_semT[(size_t)(y1c*SW__ + x0c)*CCH + c]
            + w11 * g_semT[(size_t)(y1c*SW__ + x1c)*CCH + c];
    g_X0[(size_t)col*FCIN + c] = v;
    g_G [(size_t)col*CCH  + c] = g_Ft[((size_t)n*HW_ + pix)*CCH + c];
}

// ---------------- copy MLP tail (c_inst,c_det) into pong buffer ----------------
__global__ void tail_k()
{
    const int total = NCOL*160;
    for (int i = blockIdx.x*blockDim.x + threadIdx.x; i < total; i += gridDim.x*blockDim.x) {
        int col = i / 160, r = i - col*160;
        g_X1[(size_t)col*FCIN + 256 + r] = g_X0[(size_t)col*FCIN + 256 + r];
    }
}

// ---------------- float4 bulk copy ----------------
__global__ void copy4_k(const float4* __restrict__ src, float4* __restrict__ dst, int n4)
{
    for (int i = blockIdx.x*blockDim.x + threadIdx.x; i < n4; i += gridDim.x*blockDim.x)
        dst[i] = src[i];
}

// ---------------- scatter point logits into refined feats ----------------
__global__ void scatter_k()
{
    const int col = blockIdx.x;
    const int c = threadIdx.x;
    const int n = col / PP;
    const int pix = g_idx[col];
    g_R[((size_t)n*HW_ + pix)*CCH + c] = g_P[(size_t)col*CCH + c];
}

// ---------------- x2 bilinear upsample (half-pixel, edge clamp) + relu ----------------
__global__ void upsample_k(float* __restrict__ out)
{
    const int plane = blockIdx.x;             // n*256 + c
    const int n = plane >> 8, c = plane & 255;
    const float* f = g_F + (size_t)c*NPIX + (size_t)n*HW_;
    float* o = out + 2*(size_t)NPIX + (size_t)plane*3136;
    for (int q = threadIdx.x; q < 3136; q += blockDim.x) {
        int oy = q / 56, ox = q - oy*56;
        float sy = oy*0.5f - 0.25f, sx = ox*0.5f - 0.25f;
        int iy = (int)floorf(sy), ix = (int)floorf(sx);
        float fy = sy - iy, fx = sx - ix;
        int y0c = max(iy, 0), y1c = min(iy+1, MH_-1);
        int x0c = max(ix, 0), x1c = min(ix+1, MW_-1);
        float v0 = f[y0c*MW_ + x0c]*(1.f-fx) + f[y0c*MW_ + x1c]*fx;
        float v1 = f[y1c*MW_ + x0c]*(1.f-fx) + f[y1c*MW_ + x1c]*fx;
        o[q] = fmaxf(v0*(1.f-fy) + v1*fy, 0.f);
    }
}

// ---------------- host orchestration ----------------
extern "C" void kernel_launch(void* const* d_in, const int* in_sizes, int n_in,
                              void* d_out, int out_size)
{
    (void)out_size;
    // canonical order with num_points at index 4; it may be absent (n_in==20)
    const bool has_np = (n_in >= 21);
    auto IN = [&](int i) -> const void* {
        int j = (i >= 5 && !has_np) ? i - 1 : i;
        return d_in[j];
    };
    const float* inst_feats = (const float*)IN(0);
    const float* sem_feat   = (const float*)IN(1);
    const float* rois       = (const float*)IN(2);
    const int*   labels     = (const int*)  IN(3);
    const float* w_sem  = (const float*)IN(5);  const float* b_sem  = (const float*)IN(6);
    const float* w_inst = (const float*)IN(7);  const float* b_inst = (const float*)IN(8);
    const float* w_det  = (const float*)IN(9);  const float* b_det  = (const float*)IN(10);
    const float* fc_w0  = (const float*)IN(11); const float* fc_b0  = (const float*)IN(12);
    const float* fc_w1  = (const float*)IN(13); const float* fc_b1  = (const float*)IN(14);
    const float* fc_w2  = (const float*)IN(15); const float* fc_b2  = (const float*)IN(16);
    const float* w_log  = (const float*)IN(17); const float* b_log  = (const float*)IN(18);
    const float* w_fuse = (const float*)IN(19); const float* b_fuse = (const float*)IN(20);
    float* out = (float*)d_out;

    float *p_semFT, *p_semT, *p_Ft, *p_X0, *p_X1, *p_G, *p_P, *p_R, *p_F, *p_Wid, *p_Bid;
    cudaGetSymbolAddress((void**)&p_semFT, g_semFT);
    cudaGetSymbolAddress((void**)&p_semT,  g_semT);
    cudaGetSymbolAddress((void**)&p_Ft,    g_Ft);
    cudaGetSymbolAddress((void**)&p_X0,    g_X0);
    cudaGetSymbolAddress((void**)&p_X1,    g_X1);
    cudaGetSymbolAddress((void**)&p_G,     g_G);
    cudaGetSymbolAddress((void**)&p_P,     g_P);
    cudaGetSymbolAddress((void**)&p_R,     g_R);
    cudaGetSymbolAddress((void**)&p_F,     g_F);
    cudaGetSymbolAddress((void**)&p_Wid,   g_Wid);
    cudaGetSymbolAddress((void**)&p_Bid,   g_Bid);

    // 0. stacked class weights
    wid_k<<<1, 256>>>(w_inst, b_inst, w_det, b_det);
    // 1. transposes to pixel-major
    transpose_k<<<dim3(1250, 8, 1),  dim3(32, 8)>>>(sem_feat,  p_semFT, CCH, SPIX);
    transpose_k<<<dim3(25,   8, NB), dim3(32, 8)>>>(inst_feats, p_Ft,   CCH, HW_);
    // 2. sem = relu(W_sem @ semantic + b) -> [pix][o]
    gemm_k<true, true><<<dim3(SPIX/64, 4), 256>>>(w_sem, p_semFT, p_semT, b_sem, 256, 256, 256, 256);
    // 3. label-selected instance/detail maps -> d_out[0:2*NPIX]
    class_select_k<<<NB, 256>>>(w_inst, b_inst, w_det, b_det, labels, out);
    // 4. per-ROI top-196 points
    topk_k<<<NB, 512>>>(out);
    // 5. bilinear fine + instance gather
    gather_k<<<NCOL, 256>>>(rois);
    // 6. c_inst/c_det = Wid @ G + Bid  -> X0 rows 256..415
    gemm_k<true, false><<<dim3(NCOL/64, 3), 256>>>(p_Wid, p_G, p_X0 + 256, p_Bid, 160, 256, 256, FCIN);
    // 7. copy tail into X1
    tail_k<<<4096, 256>>>();
    // 8. MLP layers (ping-pong rows 0..255)
    gemm_k<true, true ><<<dim3(NCOL/64, 4), 256>>>(fc_w0, p_X0, p_X1, fc_b0, 256, FCIN, FCIN, FCIN);
    gemm_k<true, true ><<<dim3(NCOL/64, 4), 256>>>(fc_w1, p_X1, p_X0, fc_b1, 256, FCIN, FCIN, FCIN);
    gemm_k<true, true ><<<dim3(NCOL/64, 4), 256>>>(fc_w2, p_X0, p_X1, fc_b2, 256, FCIN, FCIN, FCIN);
    // 9. point logits
    gemm_k<true, false><<<dim3(NCOL/64, 4), 256>>>(w_log, p_X1, p_P, b_log, 256, FCIN, FCIN, CCH);
    // 10. refined = instance feats with points replaced
    copy4_k<<<8192, 256>>>((const float4*)p_Ft, (float4*)p_R, (int)((size_t)NPIX*CCH/4));
    scatter_k<<<NCOL, 256>>>();
    // 11. fused = relu(W_fuse @ refined + b) -> channel-major for upsample
    gemm_k<false, true><<<dim3(NPIX/64, 4), 256>>>(w_fuse, p_R, p_F, b_fuse, 256, 256, 256, NPIX);
    // 12. x2 bilinear upsample + relu -> d_out[2*NPIX : ]
    upsample_k<<<NB*CCH, 256>>>(out);
}

// round 5
// speedup vs baseline: 1.1874x; 1.1874x over previous
#include <cuda_runtime.h>
#include <math.h>

// ---------------- problem constants ----------------
#define NB   128
#define CCH  256
#define MH_  28
#define MW_  28
#define HW_  784
#define KCLS 80
#define PP   196
#define SH__ 200
#define SW__ 200
#define SPIX 40000          // 200*200
#define FCIN 416            // C + 2K
#define NCOL (NB*PP)        // 25088 point-columns
#define NPIX (NB*HW_)       // 100352 instance pixels

// ---------------- scratch (static device globals; no allocation) ----------------
__device__ float g_semT [SPIX*CCH];            // relu(sem conv), pixel-major [pix][o]
__device__ float g_Ft [(size_t)NPIX*CCH];      // instance feats, pixel-major [n*784+pix][c]
__device__ float g_X0 [(size_t)NCOL*FCIN];     // MLP ping buffer [col][416]
__device__ float g_X1 [(size_t)NCOL*FCIN];     // MLP pong buffer [col][416]
__device__ float g_G  [(size_t)NCOL*CCH];      // gathered inst feats at points [col][c]
__device__ float g_P  [(size_t)NCOL*CCH];      // point logits [col][c]
__device__ float g_R  [(size_t)NPIX*CCH];      // refined feats [n*784+pix][c]
__device__ float g_F  [(size_t)CCH*NPIX];      // fused, channel-major [c][n*784+pix]
__device__ int   g_idx[NB*PP];                 // selected point indices
__device__ int   g_map[NPIX];                  // pixel -> point-col (-1 if untouched)
__device__ float g_Wid[160*CCH];               // stacked [w_inst; w_det]
__device__ float g_Bid[160];

// ================= 128x128x16 SGEMM, 8x8 register microtile =================
// C[M x Ncols] = op(A[M][Kd] @ B^T + bias)
// B_NMAJOR=false: B stored [col][Kd] stride ldb (K-contiguous). Requires Ncols%128==0.
// B_NMAJOR=true : B stored [k][Ncols] stride ldb (N-contiguous). Ncols%4==0, col-guarded.
// STORE_T: C[col*ldc + row], else C[row*ldc + col] (needs Ncols%128==0).
// Kd % 16 == 0. M % 8 == 0 (row-guarded).
template<bool B_NMAJOR, bool STORE_T, bool RELU>
__global__ void __launch_bounds__(256, 2)
gemm128(const float* __restrict__ A, const float* __restrict__ B,
        float* __restrict__ C, const float* __restrict__ bias,
        int M, int Kd, int Ncols, int ldb, int ldc)
{
    __shared__ float As[16][128];
    __shared__ float Bs[16][128];
    const int t  = threadIdx.x;
    const int tx = t & 15, ty = t >> 4;
    const int rowTile = blockIdx.y * 128;
    const int colTile = blockIdx.x * 128;

    // A-load mapping: row ar (0..127), k-offsets ak..ak+3 and ak+8..ak+11
    const int ar = t >> 1;
    const int ak = (t & 1) * 4;
    const bool arow_ok = (rowTile + ar) < M;
    // B N-major mapping: rows (t>>5) and 8+(t>>5), col chunk (t&31)*4
    const int bk = t >> 5;
    const int bc = (t & 31) * 4;
    const bool bcol_ok = !B_NMAJOR || (colTile + bc) < Ncols;

    float acc[8][8];
    #pragma unroll
    for (int i = 0; i < 8; i++)
        #pragma unroll
        for (int j = 0; j < 8; j++) acc[i][j] = 0.f;

    float4 ra0, ra1, rb0, rb1;
    const float4 z4 = make_float4(0.f, 0.f, 0.f, 0.f);

    // ---- prologue: load first k-tile ----
    {
        ra0 = z4; ra1 = z4;
        if (arow_ok) {
            const float* ap = A + (size_t)(rowTile + ar) * Kd + ak;
            ra0 = *reinterpret_cast<const float4*>(ap);
            ra1 = *reinterpret_cast<const float4*>(ap + 8);
        }
        if (B_NMAJOR) {
            rb0 = z4; rb1 = z4;
            if (bcol_ok) {
                rb0 = *reinterpret_cast<const float4*>(B + (size_t)bk * ldb + colTile + bc);
                rb1 = *reinterpret_cast<const float4*>(B + (size_t)(bk + 8) * ldb + colTile + bc);
            }
        } else {
            const float* bp = B + (size_t)(colTile + ar) * ldb + ak;
            rb0 = *reinterpret_cast<const float4*>(bp);
            rb1 = *reinterpret_cast<const float4*>(bp + 8);
        }
    }
    // store tile 0
    {
        As[ak+0][ar]=ra0.x; As[ak+1][ar]=ra0.y; As[ak+2][ar]=ra0.z; As[ak+3][ar]=ra0.w;
        As[ak+8][ar]=ra1.x; As[ak+9][ar]=ra1.y; As[ak+10][ar]=ra1.z; As[ak+11][ar]=ra1.w;
        if (B_NMAJOR) {
            *reinterpret_cast<float4*>(&Bs[bk][bc])     = rb0;
            *reinterpret_cast<float4*>(&Bs[bk + 8][bc]) = rb1;
        } else {
            Bs[ak+0][ar]=rb0.x; Bs[ak+1][ar]=rb0.y; Bs[ak+2][ar]=rb0.z; Bs[ak+3][ar]=rb0.w;
            Bs[ak+8][ar]=rb1.x; Bs[ak+9][ar]=rb1.y; Bs[ak+10][ar]=rb1.z; Bs[ak+11][ar]=rb1.w;
        }
    }
    __syncthreads();

    for (int k0 = 0; k0 < Kd; k0 += 16) {
        const bool more = (k0 + 16) < Kd;
        if (more) {
            const int kn = k0 + 16;
            ra0 = z4; ra1 = z4;
            if (arow_ok) {
                const float* ap = A + (size_t)(rowTile + ar) * Kd + kn + ak;
                ra0 = *reinterpret_cast<const float4*>(ap);
                ra1 = *reinterpret_cast<const float4*>(ap + 8);
            }
            if (B_NMAJOR) {
                rb0 = z4; rb1 = z4;
                if (bcol_ok) {
                    rb0 = *reinterpret_cast<const float4*>(B + (size_t)(kn + bk) * ldb + colTile + bc);
                    rb1 = *reinterpret_cast<const float4*>(B + (size_t)(kn + bk + 8) * ldb + colTile + bc);
                }
            } else {
                const float* bp = B + (size_t)(colTile + ar) * ldb + kn + ak;
                rb0 = *reinterpret_cast<const float4*>(bp);
                rb1 = *reinterpret_cast<const float4*>(bp + 8);
            }
        }
        // ---- compute 16 k-steps ----
        #pragma unroll
        for (int kk = 0; kk < 16; ++kk) {
            float4 a0 = *reinterpret_cast<const float4*>(&As[kk][ty*8]);
            float4 a1 = *reinterpret_cast<const float4*>(&As[kk][ty*8+4]);
            float4 b0 = *reinterpret_cast<const float4*>(&Bs[kk][tx*8]);
            float4 b1 = *reinterpret_cast<const float4*>(&Bs[kk][tx*8+4]);
            float av[8] = {a0.x,a0.y,a0.z,a0.w,a1.x,a1.y,a1.z,a1.w};
            float bv[8] = {b0.x,b0.y,b0.z,b0.w,b1.x,b1.y,b1.z,b1.w};
            #pragma unroll
            for (int i = 0; i < 8; i++)
                #pragma unroll
                for (int j = 0; j < 8; j++)
                    acc[i][j] = fmaf(av[i], bv[j], acc[i][j]);
        }
        if (more) {
            __syncthreads();
            As[ak+0][ar]=ra0.x; As[ak+1][ar]=ra0.y; As[ak+2][ar]=ra0.z; As[ak+3][ar]=ra0.w;
            As[ak+8][ar]=ra1.x; As[ak+9][ar]=ra1.y; As[ak+10][ar]=ra1.z; As[ak+11][ar]=ra1.w;
            if (B_NMAJOR) {
                *reinterpret_cast<float4*>(&Bs[bk][bc])     = rb0;
                *reinterpret_cast<float4*>(&Bs[bk + 8][bc]) = rb1;
            } else {
                Bs[ak+0][ar]=rb0.x; Bs[ak+1][ar]=rb0.y; Bs[ak+2][ar]=rb0.z; Bs[ak+3][ar]=rb0.w;
                Bs[ak+8][ar]=rb1.x; Bs[ak+9][ar]=rb1.y; Bs[ak+10][ar]=rb1.z; Bs[ak+11][ar]=rb1.w;
            }
            __syncthreads();
        }
    }

    // ---- epilogue ----
    const int m0 = rowTile + ty * 8;
    const int c0 = colTile + tx * 8;
    if (m0 >= M) return;   // M%8==0 -> whole microtile valid or invalid
    float bb[8];
    #pragma unroll
    for (int i = 0; i < 8; i++) bb[i] = bias[m0 + i];
    #pragma unroll
    for (int i = 0; i < 8; i++)
        #pragma unroll
        for (int j = 0; j < 8; j++) {
            float v = acc[i][j] + bb[i];
            if (RELU) v = fmaxf(v, 0.f);
            acc[i][j] = v;
        }

    if (STORE_T) {
        #pragma unroll
        for (int j = 0; j < 8; j++) {
            int col = c0 + j;
            if (B_NMAJOR && col >= Ncols) break;
            float* cp = C + (size_t)col * ldc + m0;
            *reinterpret_cast<float4*>(cp)     = make_float4(acc[0][j],acc[1][j],acc[2][j],acc[3][j]);
            *reinterpret_cast<float4*>(cp + 4) = make_float4(acc[4][j],acc[5][j],acc[6][j],acc[7][j]);
        }
    } else {
        #pragma unroll
        for (int i = 0; i < 8; i++) {
            float* cp = C + (size_t)(m0 + i) * ldc + c0;
            *reinterpret_cast<float4*>(cp)     = make_float4(acc[i][0],acc[i][1],acc[i][2],acc[i][3]);
            *reinterpret_cast<float4*>(cp + 4) = make_float4(acc[i][4],acc[i][5],acc[i][6],acc[i][7]);
        }
    }
}

// ---------------- batched 2D transpose [b][R][Cc] -> [b][Cc][R] ----------------
__global__ void transpose_k(const float* __restrict__ in, float* __restrict__ out,
                            int R, int Cc)
{
    __shared__ float tile[32][33];
    const int b = blockIdx.z;
    const float* ip = in  + (size_t)b*R*Cc;
    float*       op = out + (size_t)b*R*Cc;
    int x = blockIdx.x*32 + threadIdx.x;
    #pragma unroll
    for (int j = 0; j < 32; j += 8) {
        int y = blockIdx.y*32 + threadIdx.y + j;
        if (y < R && x < Cc) tile[threadIdx.y+j][threadIdx.x] = ip[(size_t)y*Cc + x];
    }
    __syncthreads();
    int x2 = blockIdx.y*32 + threadIdx.x;
    #pragma unroll
    for (int j = 0; j < 32; j += 8) {
        int y2 = blockIdx.x*32 + threadIdx.y + j;
        if (y2 < Cc && x2 < R) op[(size_t)y2*R + x2] = tile[threadIdx.x][threadIdx.y+j];
    }
}

// ---------------- stack class weights ----------------
__global__ void wid_k(const float* __restrict__ wi, const float* __restrict__ bi,
                      const float* __restrict__ wd, const float* __restrict__ bd)
{
    for (int i = threadIdx.x + blockIdx.x*blockDim.x; i < 160*CCH; i += blockDim.x*gridDim.x) {
        int r = i >> 8, c = i & 255;
        g_Wid[i] = (r < KCLS) ? wi[r*CCH + c] : wd[(r-KCLS)*CCH + c];
    }
    if (blockIdx.x == 0)
        for (int i = threadIdx.x; i < 160; i += blockDim.x)
            g_Bid[i] = (i < KCLS) ? bi[i] : bd[i-KCLS];
}

// ---------------- per-ROI label-selected maps ----------------
__global__ void class_select_k(const float* __restrict__ w_inst, const float* __restrict__ b_inst,
                               const float* __restrict__ w_det,  const float* __restrict__ b_det,
                               const int* __restrict__ labels, float* __restrict__ out)
{
    __shared__ float swi[CCH], swd[CCH];
    const int n = blockIdx.x;
    const int part = blockIdx.y;           // 7 parts of 112 pixels
    const int lab = labels[n];
    const int t = threadIdx.x;
    if (t < CCH) { swi[t] = w_inst[lab*CCH + t]; swd[t] = w_det[lab*CCH + t]; }
    __syncthreads();
    const float bi = b_inst[lab], bd = b_det[lab];
    const int lane = t & 31, w = t >> 5;
    const int pend = (part + 1) * 112;
    for (int p = part*112 + w; p < pend; p += 8) {
        const float* f = g_Ft + ((size_t)n*HW_ + p)*CCH;
        float si = 0.f, sd = 0.f;
        for (int c = lane; c < CCH; c += 32) {
            float v = f[c];
            si = fmaf(v, swi[c], si);
            sd = fmaf(v, swd[c], sd);
        }
        #pragma unroll
        for (int o = 16; o; o >>= 1) {
            si += __shfl_down_sync(0xffffffffu, si, o);
            sd += __shfl_down_sync(0xffffffffu, sd, o);
        }
        if (lane == 0) {
            out[n*HW_ + p]        = si + bi;   // instance_preds
            out[NPIX + n*HW_ + p] = sd + bd;   // detail_preds
        }
    }
}

// ---------------- top-196 of 784 per ROI (bitonic; set-stable vs top_k) ----------------
__global__ void topk_k(const float* __restrict__ det)
{
    __shared__ float sv[1024];
    __shared__ int   si[1024];
    const int n = blockIdx.x, t = threadIdx.x;
    for (int i = t; i < 1024; i += 512) {
        sv[i] = (i < HW_) ? det[NPIX + n*HW_ + i] : -3.4e38f;
        si[i] = i;
    }
    __syncthreads();
    for (int k2 = 2; k2 <= 1024; k2 <<= 1)
        for (int j = k2 >> 1; j > 0; j >>= 1) {
            int i = 2*t - (t & (j-1));
            int r = i + j;
            bool desc = ((i & k2) == 0);
            float vl = sv[i], vr = sv[r];
            bool sw = desc ? (vl < vr) : (vl > vr);
            if (sw) {
                sv[i] = vr; sv[r] = vl;
                int tmp = si[i]; si[i] = si[r]; si[r] = tmp;
            }
            __syncthreads();
        }
    if (t < PP) g_idx[n*PP + t] = si[t];
}

// ---------------- per-point: bilinear 'fine' + instance feat gather ----------------
__global__ void gather_k(const float* __restrict__ rois)
{
    const int col = blockIdx.x;           // n*PP + p
    const int n = col / PP;
    const int c = threadIdx.x;            // 256 threads = channels
    const int pix = g_idx[col];
    const float x1 = __ldg(rois + n*5 + 1), y1 = __ldg(rois + n*5 + 2);
    const float x2 = __ldg(rois + n*5 + 3), y2 = __ldg(rois + n*5 + 4);
    const float relx = ((pix % MW_) + 0.5f) / (float)MW_;
    const float rely = ((pix / MW_) + 0.5f) / (float)MH_;
    const float px = (x1 + relx*(x2 - x1)) * 0.25f - 0.5f;
    const float py = (y1 + rely*(y2 - y1)) * 0.25f - 0.5f;
    const float x0f = floorf(px), y0f = floorf(py);
    const float wx = px - x0f, wy = py - y0f;
    const int ix0 = (int)x0f, iy0 = (int)y0f;
    const int x0c = min(max(ix0, 0), SW__-1),   x1c = min(max(ix0+1, 0), SW__-1);
    const int y0c = min(max(iy0, 0), SH__-1),   y1c = min(max(iy0+1, 0), SH__-1);
    const float vx0 = (ix0   >= 0 && ix0   < SW__) ? 1.f : 0.f;
    const float vx1 = (ix0+1 >= 0 && ix0+1 < SW__) ? 1.f : 0.f;
    const float vy0 = (iy0   >= 0 && iy0   < SH__) ? 1.f : 0.f;
    const float vy1 = (iy0+1 >= 0 && iy0+1 < SH__) ? 1.f : 0.f;
    const float w00 = (1.f-wx)*(1.f-wy)*vx0*vy0;
    const float w10 = wx*(1.f-wy)*vx1*vy0;
    const float w01 = (1.f-wx)*wy*vx0*vy1;
    const float w11 = wx*wy*vx1*vy1;
    float v = w00 * g_semT[(size_t)(y0c*SW__ + x0c)*CCH + c]
            + w10 * g_semT[(size_t)(y0c*SW__ + x1c)*CCH + c]
            + w01 * g_semT[(size_t)(y1c*SW__ + x0c)*CCH + c]
            + w11 * g_semT[(size_t)(y1c*SW__ + x1c)*CCH + c];
    g_X0[(size_t)col*FCIN + c] = v;
    g_G [(size_t)col*CCH  + c] = g_Ft[((size_t)n*HW_ + pix)*CCH + c];
}

// ---------------- copy MLP tail (c_inst,c_det) into pong buffer ----------------
__global__ void tail_k()
{
    const int total = NCOL*160;
    for (int i = blockIdx.x*blockDim.x + threadIdx.x; i < total; i += gridDim.x*blockDim.x) {
        int col = i / 160, r = i - col*160;
        g_X1[(size_t)col*FCIN + 256 + r] = g_X0[(size_t)col*FCIN + 256 + r];
    }
}

// ---------------- pixel -> point-column map ----------------
__global__ void mapinit_k()
{
    for (int i = blockIdx.x*blockDim.x + threadIdx.x; i < NPIX; i += gridDim.x*blockDim.x)
        g_map[i] = -1;
}
__global__ void mapset_k()
{
    int col = blockIdx.x*blockDim.x + threadIdx.x;
    if (col < NCOL) {
        int n = col / PP;
        g_map[n*HW_ + g_idx[col]] = col;
    }
}
// refined[px][:] = (mapped ? point logits : original feats)
__global__ void refine_k()
{
    const int px = blockIdx.x;
    const int col = g_map[px];
    const float4* src = (col >= 0)
        ? reinterpret_cast<const float4*>(g_P + (size_t)col*CCH)
        : reinterpret_cast<const float4*>(g_Ft + (size_t)px*CCH);
    float4* dst = reinterpret_cast<float4*>(g_R + (size_t)px*CCH);
    dst[threadIdx.x] = src[threadIdx.x];
}

// ---------------- x2 bilinear upsample (half-pixel, edge clamp) + relu ----------------
__global__ void upsample_k(float* __restrict__ out)
{
    const int plane = blockIdx.x;             // n*256 + c
    const int n = plane >> 8, c = plane & 255;
    const float* f = g_F + (size_t)c*NPIX + (size_t)n*HW_;
    float* o = out + 2*(size_t)NPIX + (size_t)plane*3136;
    for (int q = threadIdx.x; q < 3136; q += blockDim.x) {
        int oy = q / 56, ox = q - oy*56;
        float sy = oy*0.5f - 0.25f, sx = ox*0.5f - 0.25f;
        int iy = (int)floorf(sy), ix = (int)floorf(sx);
        float fy = sy - iy, fx = sx - ix;
        int y0c = max(iy, 0), y1c = min(iy+1, MH_-1);
        int x0c = max(ix, 0), x1c = min(ix+1, MW_-1);
        float v0 = f[y0c*MW_ + x0c]*(1.f-fx) + f[y0c*MW_ + x1c]*fx;
        float v1 = f[y1c*MW_ + x0c]*(1.f-fx) + f[y1c*MW_ + x1c]*fx;
        o[q] = fmaxf(v0*(1.f-fy) + v1*fy, 0.f);
    }
}

// ---------------- host orchestration ----------------
extern "C" void kernel_launch(void* const* d_in, const int* in_sizes, int n_in,
                              void* d_out, int out_size)
{
    (void)out_size;
    const bool has_np = (n_in >= 21);
    auto IN = [&](int i) -> const void* {
        int j = (i >= 5 && !has_np) ? i - 1 : i;
        return d_in[j];
    };
    const float* inst_feats = (const float*)IN(0);
    const float* sem_feat   = (const float*)IN(1);
    const float* rois       = (const float*)IN(2);
    const int*   labels     = (const int*)  IN(3);
    const float* w_sem  = (const float*)IN(5);  const float* b_sem  = (const float*)IN(6);
    const float* w_inst = (const float*)IN(7);  const float* b_inst = (const float*)IN(8);
    const float* w_det  = (const float*)IN(9);  const float* b_det  = (const float*)IN(10);
    const float* fc_w0  = (const float*)IN(11); const float* fc_b0  = (const float*)IN(12);
    const float* fc_w1  = (const float*)IN(13); const float* fc_b1  = (const float*)IN(14);
    const float* fc_w2  = (const float*)IN(15); const float* fc_b2  = (const float*)IN(16);
    const float* w_log  = (const float*)IN(17); const float* b_log  = (const float*)IN(18);
    const float* w_fuse = (const float*)IN(19); const float* b_fuse = (const float*)IN(20);
    float* out = (float*)d_out;

    float *p_semT, *p_Ft, *p_X0, *p_X1, *p_G, *p_P, *p_R, *p_F, *p_Wid, *p_Bid;
    cudaGetSymbolAddress((void**)&p_semT,  g_semT);
    cudaGetSymbolAddress((void**)&p_Ft,    g_Ft);
    cudaGetSymbolAddress((void**)&p_X0,    g_X0);
    cudaGetSymbolAddress((void**)&p_X1,    g_X1);
    cudaGetSymbolAddress((void**)&p_G,     g_G);
    cudaGetSymbolAddress((void**)&p_P,     g_P);
    cudaGetSymbolAddress((void**)&p_R,     g_R);
    cudaGetSymbolAddress((void**)&p_F,     g_F);
    cudaGetSymbolAddress((void**)&p_Wid,   g_Wid);
    cudaGetSymbolAddress((void**)&p_Bid,   g_Bid);

    // 0. stacked class weights + map init (independent of everything heavy)
    wid_k<<<40, 256>>>(w_inst, b_inst, w_det, b_det);
    mapinit_k<<<392, 256>>>();
    // 1. transpose instance feats to pixel-major
    transpose_k<<<dim3(25, 8, NB), dim3(32, 8)>>>(inst_feats, p_Ft, CCH, HW_);
    // 2. sem = relu(W_sem @ semantic + b) -> [pix][o]; B read N-major straight from input
    gemm128<true, true, true><<<dim3(313, 2), 256>>>(w_sem, sem_feat, p_semT, b_sem,
                                                     256, 256, SPIX, SPIX, 256);
    // 3. label-selected instance/detail maps -> d_out[0:2*NPIX]
    class_select_k<<<dim3(NB, 7), 256>>>(w_inst, b_inst, w_det, b_det, labels, out);
    // 4. per-ROI top-196 points
    topk_k<<<NB, 512>>>(out);
    mapset_k<<<(NCOL + 255)/256, 256>>>();
    // 5. bilinear fine + instance gather
    gather_k<<<NCOL, 256>>>(rois);
    // 6. c_inst/c_det = Wid @ G + Bid  -> X0 rows 256..415
    gemm128<false, true, false><<<dim3(NCOL/128, 2), 256>>>(p_Wid, p_G, p_X0 + 256, p_Bid,
                                                            160, 256, NCOL, 256, FCIN);
    // 7. copy tail into X1
    tail_k<<<4096, 256>>>();
    // 8. MLP layers (ping-pong rows 0..255)
    gemm128<false, true, true ><<<dim3(NCOL/128, 2), 256>>>(fc_w0, p_X0, p_X1, fc_b0,
                                                            256, FCIN, NCOL, FCIN, FCIN);
    gemm128<false, true, true ><<<dim3(NCOL/128, 2), 256>>>(fc_w1, p_X1, p_X0, fc_b1,
                                                            256, FCIN, NCOL, FCIN, FCIN);
    gemm128<false, true, true ><<<dim3(NCOL/128, 2), 256>>>(fc_w2, p_X0, p_X1, fc_b2,
                                                            256, FCIN, NCOL, FCIN, FCIN);
    // 9. point logits
    gemm128<false, true, false><<<dim3(NCOL/128, 2), 256>>>(w_log, p_X1, p_P, b_log,
                                                            256, FCIN, NCOL, FCIN, CCH);
    // 10. refined = instance feats with selected points replaced (single pass via map)
    refine_k<<<NPIX, 64>>>();
    // 11. fused = relu(W_fuse @ refined + b) -> channel-major for upsample
    gemm128<false, false, true><<<dim3(NPIX/128, 2), 256>>>(w_fuse, p_R, p_F, b_fuse,
                                                            256, 256, NPIX, CCH, NPIX);
    // 12. x2 bilinear upsample + relu -> d_out[2*NPIX : ]
    upsample_k<<<NB*CCH, 256>>>(out);
}

// round 7
// speedup vs baseline: 1.8288x; 1.5401x over previous
#include <cuda_runtime.h>
#include <cstdint>
#include <math.h>

// ---------------- problem constants ----------------
#define NB   128
#define CCH  256
#define MH_  28
#define MW_  28
#define HW_  784
#define KCLS 80
#define PP   196
#define SH__ 200
#define SW__ 200
#define SPIX 40000          // 200*200
#define SPIXP 40064         // padded to 313*128
#define FCIN 416            // C + 2K
#define NCOL (NB*PP)        // 25088 point-columns
#define NPIX (NB*HW_)       // 100352 instance pixels

// ---------------- scratch (static device globals; no allocation) ----------------
__device__ float g_semFT[(size_t)SPIXP*CCH];   // transposed semantic feat [pix][c] (pad rows zero)
__device__ float g_semT [(size_t)SPIX*CCH];    // relu(sem conv) [pix][o]
__device__ float g_Ft [(size_t)NPIX*CCH];      // instance feats pixel-major
__device__ float g_X0 [(size_t)NCOL*FCIN];     // MLP ping
__device__ float g_X1 [(size_t)NCOL*FCIN];     // MLP pong
__device__ float g_G  [(size_t)NCOL*CCH];      // gathered inst feats at points
__device__ float g_P  [(size_t)NCOL*CCH];      // point logits
__device__ float g_R  [(size_t)NPIX*CCH];      // refined feats
__device__ float g_F  [(size_t)CCH*NPIX];      // fused, channel-major
__device__ int   g_idx[NB*PP];
__device__ int   g_map[NPIX];
__device__ float g_Wid[256*CCH];               // stacked [w_inst; w_det; zeros]
__device__ float g_Bid[256];

// ---------------- tf32 helpers (legacy mma.sync — valid on compute_103 base) ----------------
__device__ __forceinline__ uint32_t cvt_tf32(float f) {
    uint32_t r; asm("cvt.rna.tf32.f32 %0, %1;" : "=r"(r) : "f"(f)); return r;
}
__device__ __forceinline__ void mma8(float* c,
                                     uint32_t a0, uint32_t a1, uint32_t a2, uint32_t a3,
                                     uint32_t b0, uint32_t b1) {
    asm volatile("mma.sync.aligned.m16n8k8.row.col.f32.tf32.tf32.f32 "
                 "{%0,%1,%2,%3}, {%4,%5,%6,%7}, {%8,%9}, {%0,%1,%2,%3};"
                 : "+f"(c[0]), "+f"(c[1]), "+f"(c[2]), "+f"(c[3])
                 : "r"(a0), "r"(a1), "r"(a2), "r"(a3), "r"(b0), "r"(b1));
}

// ================= tf32 tensor-core TN GEMM =================
// C[M x Ncols] = op(A[M][Kd] @ B^T + bias)
// A row-major [M][Kd]; rows up to 128*gridDim.y must be readable (pad buffers).
// B [col][Kd] stride ldb; rows up to 128*gridDim.x must be readable (pad buffers).
// Kd % 16 == 0. STORE_T: C[n*ldc+m] (m,n guarded). else: C[m*ldc+n] (m guarded, n full).
// SMEM layout per 128-row tile: row stride 18 words, col = k8step*8 + (k&3)*2 + (k>>2)
// so fragment pairs (k, k+4) are adjacent -> LDS.64 per fragment pair.
template<bool STORE_T, bool RELU>
__global__ void __launch_bounds__(256, 2)
mgemm(const float* __restrict__ A, const float* __restrict__ B,
      float* __restrict__ C, const float* __restrict__ bias,
      int M, int Kd, int Ncols, int ldb, int ldc)
{
    __shared__ uint32_t As[128*18];
    __shared__ uint32_t Bs[128*18];
    const int t = threadIdx.x;
    const int rowTile = blockIdx.y * 128;
    const int colTile = blockIdx.x * 128;
    const int ar   = t >> 1;          // 0..127 source row within tile
    const int koff = (t & 1) * 8;     // this thread covers k koff..koff+7 (one k8 step)
    const int wid = t >> 5, lane = t & 31;
    const int wr = wid & 1, wc = wid >> 1;      // warp grid 2 x 4
    const int g = lane >> 2, q = lane & 3;

    float acc[4][4][4];
    #pragma unroll
    for (int i = 0; i < 4; i++)
        #pragma unroll
        for (int j = 0; j < 4; j++)
            #pragma unroll
            for (int r = 0; r < 4; r++) acc[i][j][r] = 0.f;

    const float* aPtr = A + (size_t)(rowTile + ar) * Kd + koff;
    const float* bPtr = B + (size_t)(colTile + ar) * ldb + koff;

    float4 ra0 = *reinterpret_cast<const float4*>(aPtr);
    float4 ra1 = *reinterpret_cast<const float4*>(aPtr + 4);
    float4 rb0 = *reinterpret_cast<const float4*>(bPtr);
    float4 rb1 = *reinterpret_cast<const float4*>(bPtr + 4);

    const int sBase = ar * 18 + koff;   // koff == k8step*8

    for (int k0 = 0; k0 < Kd; k0 += 16) {
        if (k0) __syncthreads();
        // permuted scalar STS: v0 -> pos 0,2,4,6 ; v1 -> pos 1,3,5,7
        As[sBase + 0] = cvt_tf32(ra0.x); As[sBase + 2] = cvt_tf32(ra0.y);
        As[sBase + 4] = cvt_tf32(ra0.z); As[sBase + 6] = cvt_tf32(ra0.w);
        As[sBase + 1] = cvt_tf32(ra1.x); As[sBase + 3] = cvt_tf32(ra1.y);
        As[sBase + 5] = cvt_tf32(ra1.z); As[sBase + 7] = cvt_tf32(ra1.w);
        Bs[sBase + 0] = cvt_tf32(rb0.x); Bs[sBase + 2] = cvt_tf32(rb0.y);
        Bs[sBase + 4] = cvt_tf32(rb0.z); Bs[sBase + 6] = cvt_tf32(rb0.w);
        Bs[sBase + 1] = cvt_tf32(rb1.x); Bs[sBase + 3] = cvt_tf32(rb1.y);
        Bs[sBase + 5] = cvt_tf32(rb1.z); Bs[sBase + 7] = cvt_tf32(rb1.w);
        __syncthreads();

        const bool more = (k0 + 16) < Kd;
        if (more) {
            aPtr += 16; bPtr += 16;
            ra0 = *reinterpret_cast<const float4*>(aPtr);
            ra1 = *reinterpret_cast<const float4*>(aPtr + 4);
            rb0 = *reinterpret_cast<const float4*>(bPtr);
            rb1 = *reinterpret_cast<const float4*>(bPtr + 4);
        }

        #pragma unroll
        for (int s = 0; s < 2; s++) {
            const int cb = s * 8 + q * 2;
            uint2 aF[4][2];
            #pragma unroll
            for (int i = 0; i < 4; i++) {
                const int r0 = wr * 64 + i * 16 + g;
                aF[i][0] = *reinterpret_cast<const uint2*>(&As[r0 * 18 + cb]);       // a0,a2
                aF[i][1] = *reinterpret_cast<const uint2*>(&As[(r0 + 8) * 18 + cb]); // a1,a3
            }
            #pragma unroll
            for (int j = 0; j < 4; j++) {
                const int n0 = wc * 32 + j * 8 + g;
                uint2 bF = *reinterpret_cast<const uint2*>(&Bs[n0 * 18 + cb]);       // b0,b1
                #pragma unroll
                for (int i = 0; i < 4; i++)
                    mma8(acc[i][j], aF[i][0].x, aF[i][1].x, aF[i][0].y, aF[i][1].y,
                         bF.x, bF.y);
            }
        }
    }

    // ---- epilogue ----
    #pragma unroll
    for (int i = 0; i < 4; i++) {
        const int m0 = rowTile + wr * 64 + i * 16 + g;
        const int m1 = m0 + 8;
        const float bv0 = bias[m0], bv1 = bias[m1];
        const bool m0ok = m0 < M, m1ok = m1 < M;
        #pragma unroll
        for (int j = 0; j < 4; j++) {
            const int n0 = colTile + wc * 32 + j * 8 + 2 * q;
            float v0 = acc[i][j][0] + bv0, v1 = acc[i][j][1] + bv0;
            float v2 = acc[i][j][2] + bv1, v3 = acc[i][j][3] + bv1;
            if (RELU) {
                v0 = fmaxf(v0, 0.f); v1 = fmaxf(v1, 0.f);
                v2 = fmaxf(v2, 0.f); v3 = fmaxf(v3, 0.f);
            }
            if (STORE_T) {
                if (m0ok) {
                    if (n0     < Ncols) C[(size_t)n0 * ldc + m0]     = v0;
                    if (n0 + 1 < Ncols) C[(size_t)(n0+1) * ldc + m0] = v1;
                }
                if (m1ok) {
                    if (n0     < Ncols) C[(size_t)n0 * ldc + m1]     = v2;
                    if (n0 + 1 < Ncols) C[(size_t)(n0+1) * ldc + m1] = v3;
                }
            } else {
                if (m0ok) *reinterpret_cast<float2*>(C + (size_t)m0 * ldc + n0) = make_float2(v0, v1);
                if (m1ok) *reinterpret_cast<float2*>(C + (size_t)m1 * ldc + n0) = make_float2(v2, v3);
            }
        }
    }
}

// ---------------- batched 2D transpose [b][R][Cc] -> [b][Cc][R] ----------------
__global__ void transpose_k(const float* __restrict__ in, float* __restrict__ out,
                            int R, int Cc)
{
    __shared__ float tile[32][33];
    const int b = blockIdx.z;
    const float* ip = in  + (size_t)b*R*Cc;
    float*       op = out + (size_t)b*R*Cc;
    int x = blockIdx.x*32 + threadIdx.x;
    #pragma unroll
    for (int j = 0; j < 32; j += 8) {
        int y = blockIdx.y*32 + threadIdx.y + j;
        if (y < R && x < Cc) tile[threadIdx.y+j][threadIdx.x] = ip[(size_t)y*Cc + x];
    }
    __syncthreads();
    int x2 = blockIdx.y*32 + threadIdx.x;
    #pragma unroll
    for (int j = 0; j < 32; j += 8) {
        int y2 = blockIdx.x*32 + threadIdx.y + j;
        if (y2 < Cc && x2 < R) op[(size_t)y2*R + x2] = tile[threadIdx.x][threadIdx.y+j];
    }
}

// sem transpose into padded buffer; pad rows [SPIX, SPIXP) zeroed separately
__global__ void transposeS_k(const float* __restrict__ in)
{
    __shared__ float tile[32][33];
    int x = blockIdx.x*32 + threadIdx.x;
    #pragma unroll
    for (int j = 0; j < 32; j += 8) {
        int y = blockIdx.y*32 + threadIdx.y + j;
        if (x < SPIX) tile[threadIdx.y+j][threadIdx.x] = in[(size_t)y*SPIX + x];
    }
    __syncthreads();
    int pix = blockIdx.x*32 + threadIdx.y;
    int c   = blockIdx.y*32 + threadIdx.x;
    #pragma unroll
    for (int j = 0; j < 32; j += 8) {
        if (pix + j < SPIX)
            g_semFT[(size_t)(pix + j)*CCH + c] = tile[threadIdx.x][threadIdx.y+j];
    }
}
__global__ void sempad_k()
{
    int i = blockIdx.x*blockDim.x + threadIdx.x;
    int total = (SPIXP - SPIX) * CCH;
    if (i < total) g_semFT[(size_t)SPIX*CCH + i] = 0.f;
}

// ---------------- stack class weights (zero-padded to 256 rows) ----------------
__global__ void wid_k(const float* __restrict__ wi, const float* __restrict__ bi,
                      const float* __restrict__ wd, const float* __restrict__ bd)
{
    for (int i = threadIdx.x + blockIdx.x*blockDim.x; i < 256*CCH; i += blockDim.x*gridDim.x) {
        int r = i >> 8, c = i & 255;
        g_Wid[i] = (r < KCLS) ? wi[r*CCH + c] : (r < 160 ? wd[(r-KCLS)*CCH + c] : 0.f);
    }
    if (blockIdx.x == 0)
        for (int i = threadIdx.x; i < 256; i += blockDim.x)
            g_Bid[i] = (i < KCLS) ? bi[i] : (i < 160 ? bd[i-KCLS] : 0.f);
}

// ---------------- per-ROI label-selected maps (fp32 exact; feeds topk) ----------------
__global__ void class_select_k(const float* __restrict__ w_inst, const float* __restrict__ b_inst,
                               const float* __restrict__ w_det,  const float* __restrict__ b_det,
                               const int* __restrict__ labels, float* __restrict__ out)
{
    __shared__ float swi[CCH], swd[CCH];
    const int n = blockIdx.x;
    const int part = blockIdx.y;
    const int lab = labels[n];
    const int t = threadIdx.x;
    if (t < CCH) { swi[t] = w_inst[lab*CCH + t]; swd[t] = w_det[lab*CCH + t]; }
    __syncthreads();
    const float bi = b_inst[lab], bd = b_det[lab];
    const int lane = t & 31, w = t >> 5;
    const int pend = (part + 1) * 112;
    for (int p = part*112 + w; p < pend; p += 8) {
        const float* f = g_Ft + ((size_t)n*HW_ + p)*CCH;
        float si = 0.f, sd = 0.f;
        for (int c = lane; c < CCH; c += 32) {
            float v = f[c];
            si = fmaf(v, swi[c], si);
            sd = fmaf(v, swd[c], sd);
        }
        #pragma unroll
        for (int o = 16; o; o >>= 1) {
            si += __shfl_down_sync(0xffffffffu, si, o);
            sd += __shfl_down_sync(0xffffffffu, sd, o);
        }
        if (lane == 0) {
            out[n*HW_ + p]        = si + bi;
            out[NPIX + n*HW_ + p] = sd + bd;
        }
    }
}

// ---------------- top-196 of 784 per ROI ----------------
__global__ void topk_k(const float* __restrict__ det)
{
    __shared__ float sv[1024];
    __shared__ int   si[1024];
    const int n = blockIdx.x, t = threadIdx.x;
    for (int i = t; i < 1024; i += 512) {
        sv[i] = (i < HW_) ? det[NPIX + n*HW_ + i] : -3.4e38f;
        si[i] = i;
    }
    __syncthreads();
    for (int k2 = 2; k2 <= 1024; k2 <<= 1)
        for (int j = k2 >> 1; j > 0; j >>= 1) {
            int i = 2*t - (t & (j-1));
            int r = i + j;
            bool desc = ((i & k2) == 0);
            float vl = sv[i], vr = sv[r];
            bool sw = desc ? (vl < vr) : (vl > vr);
            if (sw) {
                sv[i] = vr; sv[r] = vl;
                int tmp = si[i]; si[i] = si[r]; si[r] = tmp;
            }
            __syncthreads();
        }
    if (t < PP) g_idx[n*PP + t] = si[t];
}

// ---------------- per-point: bilinear 'fine' + instance feat gather ----------------
__global__ void gather_k(const float* __restrict__ rois)
{
    const int col = blockIdx.x;
    const int n = col / PP;
    const int c = threadIdx.x;
    const int pix = g_idx[col];
    const float x1 = __ldg(rois + n*5 + 1), y1 = __ldg(rois + n*5 + 2);
    const float x2 = __ldg(rois + n*5 + 3), y2 = __ldg(rois + n*5 + 4);
    const float relx = ((pix % MW_) + 0.5f) / (float)MW_;
    const float rely = ((pix / MW_) + 0.5f) / (float)MH_;
    const float px = (x1 + relx*(x2 - x1)) * 0.25f - 0.5f;
    const float py = (y1 + rely*(y2 - y1)) * 0.25f - 0.5f;
    const float x0f = floorf(px), y0f = floorf(py);
    const float wx = px - x0f, wy = py - y0f;
    const int ix0 = (int)x0f, iy0 = (int)y0f;
    const int x0c = min(max(ix0, 0), SW__-1),   x1c = min(max(ix0+1, 0), SW__-1);
    const int y0c = min(max(iy0, 0), SH__-1),   y1c = min(max(iy0+1, 0), SH__-1);
    const float vx0 = (ix0   >= 0 && ix0   < SW__) ? 1.f : 0.f;
    const float vx1 = (ix0+1 >= 0 && ix0+1 < SW__) ? 1.f : 0.f;
    const float vy0 = (iy0   >= 0 && iy0   < SH__) ? 1.f : 0.f;
    const float vy1 = (iy0+1 >= 0 && iy0+1 < SH__) ? 1.f : 0.f;
    const float w00 = (1.f-wx)*(1.f-wy)*vx0*vy0;
    const float w10 = wx*(1.f-wy)*vx1*vy0;
    const float w01 = (1.f-wx)*wy*vx0*vy1;
    const float w11 = wx*wy*vx1*vy1;
    float v = w00 * g_semT[(size_t)(y0c*SW__ + x0c)*CCH + c]
            + w10 * g_semT[(size_t)(y0c*SW__ + x1c)*CCH + c]
            + w01 * g_semT[(size_t)(y1c*SW__ + x0c)*CCH + c]
            + w11 * g_semT[(size_t)(y1c*SW__ + x1c)*CCH + c];
    g_X0[(size_t)col*FCIN + c] = v;
    g_G [(size_t)col*CCH  + c] = g_Ft[((size_t)n*HW_ + pix)*CCH + c];
}

// ---------------- copy MLP tail into pong buffer ----------------
__global__ void tail_k()
{
    const int total = NCOL*160;
    for (int i = blockIdx.x*blockDim.x + threadIdx.x; i < total; i += gridDim.x*blockDim.x) {
        int col = i / 160, r = i - col*160;
        g_X1[(size_t)col*FCIN + 256 + r] = g_X0[(size_t)col*FCIN + 256 + r];
    }
}

// ---------------- pixel -> point-column map, refine ----------------
__global__ void mapinit_k()
{
    for (int i = blockIdx.x*blockDim.x + threadIdx.x; i < NPIX; i += gridDim.x*blockDim.x)
        g_map[i] = -1;
}
__global__ void mapset_k()
{
    int col = blockIdx.x*blockDim.x + threadIdx.x;
    if (col < NCOL) {
        int n = col / PP;
        g_map[n*HW_ + g_idx[col]] = col;
    }
}
__global__ void refine_k()
{
    const int px = blockIdx.x;
    const int col = g_map[px];
    const float4* src = (col >= 0)
        ? reinterpret_cast<const float4*>(g_P + (size_t)col*CCH)
        : reinterpret_cast<const float4*>(g_Ft + (size_t)px*CCH);
    float4* dst = reinterpret_cast<float4*>(g_R + (size_t)px*CCH);
    dst[threadIdx.x] = src[threadIdx.x];
}

// ---------------- x2 bilinear upsample + relu ----------------
__global__ void upsample_k(float* __restrict__ out)
{
    const int plane = blockIdx.x;
    const int n = plane >> 8, c = plane & 255;
    const float* f = g_F + (size_t)c*NPIX + (size_t)n*HW_;
    float* o = out + 2*(size_t)NPIX + (size_t)plane*3136;
    for (int q = threadIdx.x; q < 3136; q += blockDim.x) {
        int oy = q / 56, ox = q - oy*56;
        float sy = oy*0.5f - 0.25f, sx = ox*0.5f - 0.25f;
        int iy = (int)floorf(sy), ix = (int)floorf(sx);
        float fy = sy - iy, fx = sx - ix;
        int y0c = max(iy, 0), y1c = min(iy+1, MH_-1);
        int x0c = max(ix, 0), x1c = min(ix+1, MW_-1);
        float v0 = f[y0c*MW_ + x0c]*(1.f-fx) + f[y0c*MW_ + x1c]*fx;
        float v1 = f[y1c*MW_ + x0c]*(1.f-fx) + f[y1c*MW_ + x1c]*fx;
        o[q] = fmaxf(v0*(1.f-fy) + v1*fy, 0.f);
    }
}

// ---------------- host orchestration ----------------
extern "C" void kernel_launch(void* const* d_in, const int* in_sizes, int n_in,
                              void* d_out, int out_size)
{
    (void)out_size;
    const bool has_np = (n_in >= 21);
    auto IN = [&](int i) -> const void* {
        int j = (i >= 5 && !has_np) ? i - 1 : i;
        return d_in[j];
    };
    const float* inst_feats = (const float*)IN(0);
    const float* sem_feat   = (const float*)IN(1);
    const float* rois       = (const float*)IN(2);
    const int*   labels     = (const int*)  IN(3);
    const float* w_sem  = (const float*)IN(5);  const float* b_sem  = (const float*)IN(6);
    const float* w_inst = (const float*)IN(7);  const float* b_inst = (const float*)IN(8);
    const float* w_det  = (const float*)IN(9);  const float* b_det  = (const float*)IN(10);
    const float* fc_w0  = (const float*)IN(11); const float* fc_b0  = (const float*)IN(12);
    const float* fc_w1  = (const float*)IN(13); const float* fc_b1  = (const float*)IN(14);
    const float* fc_w2  = (const float*)IN(15); const float* fc_b2  = (const float*)IN(16);
    const float* w_log  = (const float*)IN(17); const float* b_log  = (const float*)IN(18);
    const float* w_fuse = (const float*)IN(19); const float* b_fuse = (const float*)IN(20);
    float* out = (float*)d_out;

    float *p_semFT, *p_semT, *p_Ft, *p_X0, *p_X1, *p_G, *p_P, *p_R, *p_F, *p_Wid, *p_Bid;
    cudaGetSymbolAddress((void**)&p_semFT, g_semFT);
    cudaGetSymbolAddress((void**)&p_semT,  g_semT);
    cudaGetSymbolAddress((void**)&p_Ft,    g_Ft);
    cudaGetSymbolAddress((void**)&p_X0,    g_X0);
    cudaGetSymbolAddress((void**)&p_X1,    g_X1);
    cudaGetSymbolAddress((void**)&p_G,     g_G);
    cudaGetSymbolAddress((void**)&p_P,     g_P);
    cudaGetSymbolAddress((void**)&p_R,     g_R);
    cudaGetSymbolAddress((void**)&p_F,     g_F);
    cudaGetSymbolAddress((void**)&p_Wid,   g_Wid);
    cudaGetSymbolAddress((void**)&p_Bid,   g_Bid);

    // 0. stacked class weights + map init + sem pad rows
    wid_k<<<64, 256>>>(w_inst, b_inst, w_det, b_det);
    mapinit_k<<<392, 256>>>();
    sempad_k<<<((SPIXP-SPIX)*CCH + 255)/256, 256>>>();
    // 1. transposes to pixel-major
    transpose_k<<<dim3(25, 8, NB), dim3(32, 8)>>>(inst_feats, p_Ft, CCH, HW_);
    transposeS_k<<<dim3(1250, 8), dim3(32, 8)>>>(sem_feat);
    // 2. sem = relu(W_sem @ semantic + b)   [tf32 tensor cores]
    mgemm<true, true><<<dim3(313, 2), 256>>>(w_sem, p_semFT, p_semT, b_sem,
                                             256, 256, SPIX, 256, 256);
    // 3. label-selected maps -> d_out[0:2*NPIX] (fp32 exact, feeds topk)
    class_select_k<<<dim3(NB, 7), 256>>>(w_inst, b_inst, w_det, b_det, labels, out);
    // 4. per-ROI top-196 points
    topk_k<<<NB, 512>>>(out);
    mapset_k<<<(NCOL + 255)/256, 256>>>();
    // 5. bilinear fine + instance gather
    gather_k<<<NCOL, 256>>>(rois);
    // 6. c_inst/c_det -> X0 rows 256..415
    mgemm<true, false><<<dim3(196, 2), 256>>>(p_Wid, p_G, p_X0 + 256, p_Bid,
                                              160, 256, NCOL, 256, FCIN);
    // 7. copy tail into X1
    tail_k<<<4096, 256>>>();
    // 8. MLP layers
    mgemm<true, true ><<<dim3(196, 2), 256>>>(fc_w0, p_X0, p_X1, fc_b0,
                                              256, FCIN, NCOL, FCIN, FCIN);
    mgemm<true, true ><<<dim3(196, 2), 256>>>(fc_w1, p_X1, p_X0, fc_b1,
                                              256, FCIN, NCOL, FCIN, FCIN);
    mgemm<true, true ><<<dim3(196, 2), 256>>>(fc_w2, p_X0, p_X1, fc_b2,
                                              256, FCIN, NCOL, FCIN, FCIN);
    // 9. point logits
    mgemm<true, false><<<dim3(196, 2), 256>>>(w_log, p_X1, p_P, b_log,
                                              256, FCIN, NCOL, FCIN, CCH);
    // 10. refined feats
    refine_k<<<NPIX, 64>>>();
    // 11. fused = relu(W_fuse @ refined + b), channel-major out
    mgemm<false, true><<<dim3(784, 2), 256>>>(w_fuse, p_R, p_F, b_fuse,
                                              256, 256, NPIX, CCH, NPIX);
    // 12. x2 bilinear upsample + relu
    upsample_k<<<NB*CCH, 256>>>(out);
}

// round 8
// speedup vs baseline: 2.0978x; 1.1471x over previous
#include <cuda_runtime.h>
#include <cstdint>
#include <math.h>

// ---------------- problem constants ----------------
#define NB   128
#define CCH  256
#define MH_  28
#define MW_  28
#define HW_  784
#define KCLS 80
#define PP   196
#define SH__ 200
#define SW__ 200
#define SPIX 40000          // 200*200
#define FCIN 416            // C + 2K
#define NCOL (NB*PP)        // 25088 point-columns
#define NPIX (NB*HW_)       // 100352 instance pixels

// ---------------- scratch (static device globals; no allocation) ----------------
__device__ float g_semT [(size_t)SPIX*CCH];    // relu(sem conv) [pix][o]
__device__ float g_Ft [(size_t)NPIX*CCH];      // instance feats pixel-major
__device__ float g_X0 [(size_t)NCOL*FCIN];     // MLP ping
__device__ float g_X1 [(size_t)NCOL*FCIN];     // MLP pong
__device__ float g_P  [(size_t)NCOL*CCH];      // point logits
__device__ float g_F  [(size_t)CCH*NPIX];      // fused, channel-major
__device__ int   g_idx[NB*PP];
__device__ int   g_map[NPIX];
__device__ float g_Wid[256*CCH];               // stacked [w_inst; w_det; zeros]
__device__ float g_Bid[256];

// ---------------- tf32 helpers (legacy mma.sync — valid on compute_103 base) ----------------
__device__ __forceinline__ uint32_t cvt_tf32(float f) {
    uint32_t r; asm("cvt.rna.tf32.f32 %0, %1;" : "=r"(r) : "f"(f)); return r;
}
__device__ __forceinline__ void mma8(float* c,
                                     uint32_t a0, uint32_t a1, uint32_t a2, uint32_t a3,
                                     uint32_t b0, uint32_t b1) {
    asm volatile("mma.sync.aligned.m16n8k8.row.col.f32.tf32.tf32.f32 "
                 "{%0,%1,%2,%3}, {%4,%5,%6,%7}, {%8,%9}, {%0,%1,%2,%3};"
                 : "+f"(c[0]), "+f"(c[1]), "+f"(c[2]), "+f"(c[3])
                 : "r"(a0), "r"(a1), "r"(a2), "r"(a3), "r"(b0), "r"(b1));
}

// ================= tf32 tensor-core TN GEMM =================
// C[M x Ncols] = op(A[M][Kd] @ B^T + bias)
// A row-major [M][Kd]; rows 128*gridDim.y must be readable (buffers padded).
// BMODE 0: B[col][Kd] stride ldb (rows up to 128*gridDim.x readable)
// BMODE 1: B[k][Ncols] stride ldb (N-major, col load-guarded vs Ncols)
// BMODE 2: row = gathered instance pixel: aux=g_idx, B=g_Ft
// BMODE 3: row = refine select: aux=g_map, P=g_P, B=g_Ft
// Kd % 16 == 0. M % 4 == 0.
// STORE_T: C[n*ldc+m] (m,n guarded); C2 optional dup. else: C[m*ldc+n] (m guarded, Ncols%128==0).
// SMEM tile layout: row stride 18 words, pos(k) within k8 group = ((k&3)<<1)+((k>>2)&1).
template<int BMODE, bool STORE_T, bool RELU>
__global__ void __launch_bounds__(256, 2)
mgemm(const float* __restrict__ A, const float* __restrict__ B,
      float* __restrict__ C, float* __restrict__ C2,
      const float* __restrict__ bias,
      const float* __restrict__ P, const int* __restrict__ aux,
      int M, int Kd, int Ncols, int ldb, int ldc)
{
    __shared__ uint32_t shb[2*128*18];
    uint32_t* As = shb;
    uint32_t* Bs = shb + 128*18;
    const int t = threadIdx.x;
    const int rowTile = blockIdx.y * 128;
    const int colTile = blockIdx.x * 128;
    const int ar   = t >> 1;          // 0..127 row within tile (A and B modes 0/2/3)
    const int koff = (t & 1) * 8;     // k sub-block
    const int wid = t >> 5, lane = t & 31;
    const int wr = wid & 1, wc = wid >> 1;      // warp grid 2 x 4
    const int g = lane >> 2, q = lane & 3;
    // BMODE 1 mapping
    const int bk = t >> 5;            // k row 0..7 (and +8)
    const int bc = (lane) * 4;        // col chunk
    const bool bok = (BMODE != 1) || (colTile + bc < Ncols);

    float acc[4][4][4];
    #pragma unroll
    for (int i = 0; i < 4; i++)
        #pragma unroll
        for (int j = 0; j < 4; j++)
            #pragma unroll
            for (int r = 0; r < 4; r++) acc[i][j][r] = 0.f;

    // ---- B row pointer (modes 0/2/3) ----
    const float* bRow = nullptr;
    if (BMODE == 0) {
        bRow = B + (size_t)(colTile + ar) * ldb;
    } else if (BMODE == 2) {
        int col = colTile + ar;
        int n = col / PP;
        bRow = B + ((size_t)n * HW_ + aux[col]) * CCH;
    } else if (BMODE == 3) {
        int px = colTile + ar;
        int c2 = aux[px];
        bRow = (c2 >= 0) ? (P + (size_t)c2 * CCH) : (B + (size_t)px * CCH);
    }
    const float* aPtr = A + (size_t)(rowTile + ar) * Kd + koff;
    const float* bPtr = (BMODE != 1) ? (bRow + koff) : nullptr;

    const float4 z4 = make_float4(0.f, 0.f, 0.f, 0.f);
    float4 ra0 = *reinterpret_cast<const float4*>(aPtr);
    float4 ra1 = *reinterpret_cast<const float4*>(aPtr + 4);
    float4 rb0, rb1;
    if (BMODE == 1) {
        rb0 = bok ? *reinterpret_cast<const float4*>(B + (size_t)bk * ldb + colTile + bc) : z4;
        rb1 = bok ? *reinterpret_cast<const float4*>(B + (size_t)(bk + 8) * ldb + colTile + bc) : z4;
    } else {
        rb0 = *reinterpret_cast<const float4*>(bPtr);
        rb1 = *reinterpret_cast<const float4*>(bPtr + 4);
    }

    const int sBase = ar * 18 + koff;
    const int p1 = ((bk & 3) << 1) + ((bk >> 2) & 1);   // BMODE 1 k-position

    for (int k0 = 0; k0 < Kd; k0 += 16) {
        if (k0) __syncthreads();
        As[sBase + 0] = cvt_tf32(ra0.x); As[sBase + 2] = cvt_tf32(ra0.y);
        As[sBase + 4] = cvt_tf32(ra0.z); As[sBase + 6] = cvt_tf32(ra0.w);
        As[sBase + 1] = cvt_tf32(ra1.x); As[sBase + 3] = cvt_tf32(ra1.y);
        As[sBase + 5] = cvt_tf32(ra1.z); As[sBase + 7] = cvt_tf32(ra1.w);
        if (BMODE == 1) {
            Bs[(bc+0)*18 + p1] = cvt_tf32(rb0.x);
            Bs[(bc+1)*18 + p1] = cvt_tf32(rb0.y);
            Bs[(bc+2)*18 + p1] = cvt_tf32(rb0.z);
            Bs[(bc+3)*18 + p1] = cvt_tf32(rb0.w);
            Bs[(bc+0)*18 + p1 + 8] = cvt_tf32(rb1.x);
            Bs[(bc+1)*18 + p1 + 8] = cvt_tf32(rb1.y);
            Bs[(bc+2)*18 + p1 + 8] = cvt_tf32(rb1.z);
            Bs[(bc+3)*18 + p1 + 8] = cvt_tf32(rb1.w);
        } else {
            Bs[sBase + 0] = cvt_tf32(rb0.x); Bs[sBase + 2] = cvt_tf32(rb0.y);
            Bs[sBase + 4] = cvt_tf32(rb0.z); Bs[sBase + 6] = cvt_tf32(rb0.w);
            Bs[sBase + 1] = cvt_tf32(rb1.x); Bs[sBase + 3] = cvt_tf32(rb1.y);
            Bs[sBase + 5] = cvt_tf32(rb1.z); Bs[sBase + 7] = cvt_tf32(rb1.w);
        }
        __syncthreads();

        const bool more = (k0 + 16) < Kd;
        if (more) {
            const int kn = k0 + 16;
            aPtr += 16;
            ra0 = *reinterpret_cast<const float4*>(aPtr);
            ra1 = *reinterpret_cast<const float4*>(aPtr + 4);
            if (BMODE == 1) {
                rb0 = bok ? *reinterpret_cast<const float4*>(B + (size_t)(kn + bk) * ldb + colTile + bc) : z4;
                rb1 = bok ? *reinterpret_cast<const float4*>(B + (size_t)(kn + bk + 8) * ldb + colTile + bc) : z4;
            } else {
                bPtr += 16;
                rb0 = *reinterpret_cast<const float4*>(bPtr);
                rb1 = *reinterpret_cast<const float4*>(bPtr + 4);
            }
        }

        #pragma unroll
        for (int s = 0; s < 2; s++) {
            const int cb = s * 8 + q * 2;
            uint2 aF[4][2];
            #pragma unroll
            for (int i = 0; i < 4; i++) {
                const int r0 = wr * 64 + i * 16 + g;
                aF[i][0] = *reinterpret_cast<const uint2*>(&As[r0 * 18 + cb]);
                aF[i][1] = *reinterpret_cast<const uint2*>(&As[(r0 + 8) * 18 + cb]);
            }
            #pragma unroll
            for (int j = 0; j < 4; j++) {
                const int n0 = wc * 32 + j * 8 + g;
                uint2 bF = *reinterpret_cast<const uint2*>(&Bs[n0 * 18 + cb]);
                #pragma unroll
                for (int i = 0; i < 4; i++)
                    mma8(acc[i][j], aF[i][0].x, aF[i][1].x, aF[i][0].y, aF[i][1].y,
                         bF.x, bF.y);
            }
        }
    }

    // ---- bias + relu in registers ----
    #pragma unroll
    for (int i = 0; i < 4; i++) {
        const int m0 = rowTile + wr * 64 + i * 16 + g;
        const float bv0 = bias[m0], bv1 = bias[m0 + 8];
        #pragma unroll
        for (int j = 0; j < 4; j++) {
            acc[i][j][0] += bv0; acc[i][j][1] += bv0;
            acc[i][j][2] += bv1; acc[i][j][3] += bv1;
            if (RELU) {
                acc[i][j][0] = fmaxf(acc[i][j][0], 0.f);
                acc[i][j][1] = fmaxf(acc[i][j][1], 0.f);
                acc[i][j][2] = fmaxf(acc[i][j][2], 0.f);
                acc[i][j][3] = fmaxf(acc[i][j][3], 0.f);
            }
        }
    }

    // ---- SMEM-staged coalesced epilogue (4 passes of 32 cols / 32 rows) ----
    float* stg = reinterpret_cast<float*>(shb);   // stride 132; 32*132*4 B <= 18 KB
    #pragma unroll
    for (int pass = 0; pass < 4; pass++) {
        __syncthreads();
        if (STORE_T) {
            if (wc == pass) {
                #pragma unroll
                for (int i = 0; i < 4; i++) {
                    const int mA = wr * 64 + i * 16 + g;
                    #pragma unroll
                    for (int j = 0; j < 4; j++) {
                        const int cl = j * 8 + 2 * q;
                        stg[cl * 132 + mA]           = acc[i][j][0];
                        stg[(cl + 1) * 132 + mA]     = acc[i][j][1];
                        stg[cl * 132 + mA + 8]       = acc[i][j][2];
                        stg[(cl + 1) * 132 + mA + 8] = acc[i][j][3];
                    }
                }
            }
            __syncthreads();
            const int cc = t >> 3;
            const int n = colTile + pass * 32 + cc;
            if (n < Ncols) {
                #pragma unroll
                for (int it = 0; it < 4; it++) {
                    const int ml = (t & 7) * 4 + it * 32;
                    const int m = rowTile + ml;
                    if (m < M) {
                        float4 v = *reinterpret_cast<float4*>(&stg[cc * 132 + ml]);
                        *reinterpret_cast<float4*>(C + (size_t)n * ldc + m) = v;
                        if (C2) *reinterpret_cast<float4*>(C2 + (size_t)n * ldc + m) = v;
                    }
                }
            }
        } else {
            if (wr == (pass >> 1)) {
                #pragma unroll
                for (int ii = 0; ii < 2; ii++) {
                    const int i = (pass & 1) * 2 + ii;
                    const int mA = i * 16 + g - (pass & 1) * 32;   // 0..23
                    #pragma unroll
                    for (int j = 0; j < 4; j++) {
                        const int cl = wc * 32 + j * 8 + 2 * q;
                        stg[mA * 132 + cl]            = acc[i][j][0];
                        stg[mA * 132 + cl + 1]        = acc[i][j][1];
                        stg[(mA + 8) * 132 + cl]      = acc[i][j][2];
                        stg[(mA + 8) * 132 + cl + 1]  = acc[i][j][3];
                    }
                }
            }
            __syncthreads();
            const int rr = t >> 3;
            const int m = rowTile + pass * 32 + rr;
            #pragma unroll
            for (int it = 0; it < 4; it++) {
                const int nl = (t & 7) * 4 + it * 32;
                if (m < M) {
                    float4 v = *reinterpret_cast<float4*>(&stg[rr * 132 + nl]);
                    *reinterpret_cast<float4*>(C + (size_t)m * ldc + colTile + nl) = v;
                }
            }
        }
    }
}

// ---------------- batched 2D transpose [b][R][Cc] -> [b][Cc][R] ----------------
__global__ void transpose_k(const float* __restrict__ in, float* __restrict__ out,
                            int R, int Cc)
{
    __shared__ float tile[32][33];
    const int b = blockIdx.z;
    const float* ip = in  + (size_t)b*R*Cc;
    float*       op = out + (size_t)b*R*Cc;
    int x = blockIdx.x*32 + threadIdx.x;
    #pragma unroll
    for (int j = 0; j < 32; j += 8) {
        int y = blockIdx.y*32 + threadIdx.y + j;
        if (y < R && x < Cc) tile[threadIdx.y+j][threadIdx.x] = ip[(size_t)y*Cc + x];
    }
    __syncthreads();
    int x2 = blockIdx.y*32 + threadIdx.x;
    #pragma unroll
    for (int j = 0; j < 32; j += 8) {
        int y2 = blockIdx.x*32 + threadIdx.y + j;
        if (y2 < Cc && x2 < R) op[(size_t)y2*R + x2] = tile[threadIdx.x][threadIdx.y+j];
    }
}

// ---------------- stack class weights (zero-padded to 256 rows) ----------------
__global__ void wid_k(const float* __restrict__ wi, const float* __restrict__ bi,
                      const float* __restrict__ wd, const float* __restrict__ bd)
{
    for (int i = threadIdx.x + blockIdx.x*blockDim.x; i < 256*CCH; i += blockDim.x*gridDim.x) {
        int r = i >> 8, c = i & 255;
        g_Wid[i] = (r < KCLS) ? wi[r*CCH + c] : (r < 160 ? wd[(r-KCLS)*CCH + c] : 0.f);
    }
    if (blockIdx.x == 0)
        for (int i = threadIdx.x; i < 256; i += blockDim.x)
            g_Bid[i] = (i < KCLS) ? bi[i] : (i < 160 ? bd[i-KCLS] : 0.f);
}

// ---------------- per-ROI label-selected maps (fp32 exact; feeds topk) ----------------
__global__ void class_select_k(const float* __restrict__ w_inst, const float* __restrict__ b_inst,
                               const float* __restrict__ w_det,  const float* __restrict__ b_det,
                               const int* __restrict__ labels, float* __restrict__ out)
{
    __shared__ float swi[CCH], swd[CCH];
    const int n = blockIdx.x;
    const int part = blockIdx.y;
    const int lab = labels[n];
    const int t = threadIdx.x;
    if (t < CCH) { swi[t] = w_inst[lab*CCH + t]; swd[t] = w_det[lab*CCH + t]; }
    __syncthreads();
    const float bi = b_inst[lab], bd = b_det[lab];
    const int lane = t & 31, w = t >> 5;
    const int pend = (part + 1) * 112;
    for (int p = part*112 + w; p < pend; p += 8) {
        const float* f = g_Ft + ((size_t)n*HW_ + p)*CCH;
        float si = 0.f, sd = 0.f;
        for (int c = lane; c < CCH; c += 32) {
            float v = f[c];
            si = fmaf(v, swi[c], si);
            sd = fmaf(v, swd[c], sd);
        }
        #pragma unroll
        for (int o = 16; o; o >>= 1) {
            si += __shfl_down_sync(0xffffffffu, si, o);
            sd += __shfl_down_sync(0xffffffffu, sd, o);
        }
        if (lane == 0) {
            out[n*HW_ + p]        = si + bi;
            out[NPIX + n*HW_ + p] = sd + bd;
        }
    }
}

// ---------------- top-196 of 784 per ROI ----------------
__global__ void topk_k(const float* __restrict__ det)
{
    __shared__ float sv[1024];
    __shared__ int   si[1024];
    const int n = blockIdx.x, t = threadIdx.x;
    for (int i = t; i < 1024; i += 512) {
        sv[i] = (i < HW_) ? det[NPIX + n*HW_ + i] : -3.4e38f;
        si[i] = i;
    }
    __syncthreads();
    for (int k2 = 2; k2 <= 1024; k2 <<= 1)
        for (int j = k2 >> 1; j > 0; j >>= 1) {
            int i = 2*t - (t & (j-1));
            int r = i + j;
            bool desc = ((i & k2) == 0);
            float vl = sv[i], vr = sv[r];
            bool sw = desc ? (vl < vr) : (vl > vr);
            if (sw) {
                sv[i] = vr; sv[r] = vl;
                int tmp = si[i]; si[i] = si[r]; si[r] = tmp;
            }
            __syncthreads();
        }
    if (t < PP) g_idx[n*PP + t] = si[t];
}

// ---------------- per-point: bilinear 'fine' into X0 rows 0..255 ----------------
__global__ void gather_k(const float* __restrict__ rois)
{
    const int col = blockIdx.x;
    const int n = col / PP;
    const int c = threadIdx.x;
    const int pix = g_idx[col];
    const float x1 = __ldg(rois + n*5 + 1), y1 = __ldg(rois + n*5 + 2);
    const float x2 = __ldg(rois + n*5 + 3), y2 = __ldg(rois + n*5 + 4);
    const float relx = ((pix % MW_) + 0.5f) / (float)MW_;
    const float rely = ((pix / MW_) + 0.5f) / (float)MH_;
    const float px = (x1 + relx*(x2 - x1)) * 0.25f - 0.5f;
    const float py = (y1 + rely*(y2 - y1)) * 0.25f - 0.5f;
    const float x0f = floorf(px), y0f = floorf(py);
    const float wx = px - x0f, wy = py - y0f;
    const int ix0 = (int)x0f, iy0 = (int)y0f;
    const int x0c = min(max(ix0, 0), SW__-1),   x1c = min(max(ix0+1, 0), SW__-1);
    const int y0c = min(max(iy0, 0), SH__-1),   y1c = min(max(iy0+1, 0), SH__-1);
    const float vx0 = (ix0   >= 0 && ix0   < SW__) ? 1.f : 0.f;
    const float vx1 = (ix0+1 >= 0 && ix0+1 < SW__) ? 1.f : 0.f;
    const float vy0 = (iy0   >= 0 && iy0   < SH__) ? 1.f : 0.f;
    const float vy1 = (iy0+1 >= 0 && iy0+1 < SH__) ? 1.f : 0.f;
    const float w00 = (1.f-wx)*(1.f-wy)*vx0*vy0;
    const float w10 = wx*(1.f-wy)*vx1*vy0;
    const float w01 = (1.f-wx)*wy*vx0*vy1;
    const float w11 = wx*wy*vx1*vy1;
    float v = w00 * g_semT[(size_t)(y0c*SW__ + x0c)*CCH + c]
            + w10 * g_semT[(size_t)(y0c*SW__ + x1c)*CCH + c]
            + w01 * g_semT[(size_t)(y1c*SW__ + x0c)*CCH + c]
            + w11 * g_semT[(size_t)(y1c*SW__ + x1c)*CCH + c];
    g_X0[(size_t)col*FCIN + c] = v;
}

// ---------------- pixel -> point-column map ----------------
__global__ void mapinit_k()
{
    for (int i = blockIdx.x*blockDim.x + threadIdx.x; i < NPIX; i += gridDim.x*blockDim.x)
        g_map[i] = -1;
}
__global__ void mapset_k()
{
    int col = blockIdx.x*blockDim.x + threadIdx.x;
    if (col < NCOL) {
        int n = col / PP;
        g_map[n*HW_ + g_idx[col]] = col;
    }
}

// ---------------- x2 bilinear upsample + relu (SMEM plane cache) ----------------
__global__ void upsample_k(float* __restrict__ out)
{
    __shared__ float sf[HW_];
    const int plane = blockIdx.x;
    const int n = plane >> 8, c = plane & 255;
    const float* f = g_F + (size_t)c*NPIX + (size_t)n*HW_;
    const int t = threadIdx.x;
    for (int i = t; i < HW_; i += blockDim.x) sf[i] = f[i];
    __syncthreads();
    float* o = out + 2*(size_t)NPIX + (size_t)plane*3136;
    for (int q4 = t; q4 < 784; q4 += blockDim.x) {   // 56x56 = 784 float4
        const int oy = q4 / 14;
        const int xb = (q4 - oy*14) * 4;
        const float sy = oy*0.5f - 0.25f;
        const int iy = (int)floorf(sy);
        const float fy = sy - iy;
        const int y0c = max(iy, 0), y1c = min(iy+1, MH_-1);
        float4 v;
        float* vp = &v.x;
        #pragma unroll
        for (int j = 0; j < 4; j++) {
            const int ox = xb + j;
            const float sx = ox*0.5f - 0.25f;
            const int ix = (int)floorf(sx);
            const float fx = sx - ix;
            const int x0c = max(ix, 0), x1c = min(ix+1, MW_-1);
            float v0 = sf[y0c*MW_ + x0c]*(1.f-fx) + sf[y0c*MW_ + x1c]*fx;
            float v1 = sf[y1c*MW_ + x0c]*(1.f-fx) + sf[y1c*MW_ + x1c]*fx;
            vp[j] = fmaxf(v0*(1.f-fy) + v1*fy, 0.f);
        }
        *reinterpret_cast<float4*>(o + oy*56 + xb) = v;
    }
}

// ---------------- host orchestration ----------------
extern "C" void kernel_launch(void* const* d_in, const int* in_sizes, int n_in,
                              void* d_out, int out_size)
{
    (void)out_size;
    const bool has_np = (n_in >= 21);
    auto IN = [&](int i) -> const void* {
        int j = (i >= 5 && !has_np) ? i - 1 : i;
        return d_in[j];
    };
    const float* inst_feats = (const float*)IN(0);
    const float* sem_feat   = (const float*)IN(1);
    const float* rois       = (const float*)IN(2);
    const int*   labels     = (const int*)  IN(3);
    const float* w_sem  = (const float*)IN(5);  const float* b_sem  = (const float*)IN(6);
    const float* w_inst = (const float*)IN(7);  const float* b_inst = (const float*)IN(8);
    const float* w_det  = (const float*)IN(9);  const float* b_det  = (const float*)IN(10);
    const float* fc_w0  = (const float*)IN(11); const float* fc_b0  = (const float*)IN(12);
    const float* fc_w1  = (const float*)IN(13); const float* fc_b1  = (const float*)IN(14);
    const float* fc_w2  = (const float*)IN(15); const float* fc_b2  = (const float*)IN(16);
    const float* w_log  = (const float*)IN(17); const float* b_log  = (const float*)IN(18);
    const float* w_fuse = (const float*)IN(19); const float* b_fuse = (const float*)IN(20);
    float* out = (float*)d_out;

    float *p_semT, *p_Ft, *p_X0, *p_X1, *p_P, *p_F, *p_Wid, *p_Bid;
    int *p_idx, *p_map;
    cudaGetSymbolAddress((void**)&p_semT,  g_semT);
    cudaGetSymbolAddress((void**)&p_Ft,    g_Ft);
    cudaGetSymbolAddress((void**)&p_X0,    g_X0);
    cudaGetSymbolAddress((void**)&p_X1,    g_X1);
    cudaGetSymbolAddress((void**)&p_P,     g_P);
    cudaGetSymbolAddress((void**)&p_F,     g_F);
    cudaGetSymbolAddress((void**)&p_Wid,   g_Wid);
    cudaGetSymbolAddress((void**)&p_Bid,   g_Bid);
    cudaGetSymbolAddress((void**)&p_idx,   g_idx);
    cudaGetSymbolAddress((void**)&p_map,   g_map);

    // 0. stacked class weights + map init
    wid_k<<<64, 256>>>(w_inst, b_inst, w_det, b_det);
    mapinit_k<<<392, 256>>>();
    // 1. transpose instance feats to pixel-major
    transpose_k<<<dim3(25, 8, NB), dim3(32, 8)>>>(inst_feats, p_Ft, CCH, HW_);
    // 2. sem = relu(W_sem @ semantic + b)  [B read N-major straight from input]
    mgemm<1, true, true><<<dim3(313, 2), 256>>>(w_sem, sem_feat, p_semT, nullptr, b_sem,
                                                nullptr, nullptr, 256, 256, SPIX, SPIX, 256);
    // 3. label-selected maps -> d_out[0:2*NPIX] (fp32 exact, feeds topk)
    class_select_k<<<dim3(NB, 7), 256>>>(w_inst, b_inst, w_det, b_det, labels, out);
    // 4. per-ROI top-196 points
    topk_k<<<NB, 512>>>(out);
    mapset_k<<<(NCOL + 255)/256, 256>>>();
    // 5. bilinear fine -> X0 rows 0..255
    gather_k<<<NCOL, 256>>>(rois);
    // 6. c_inst/c_det -> X0 & X1 rows 256..415 (B gathered via g_idx, dual store)
    mgemm<2, true, false><<<dim3(196, 2), 256>>>(p_Wid, p_Ft, p_X0 + 256, p_X1 + 256, p_Bid,
                                                 nullptr, p_idx, 160, 256, NCOL, 0, FCIN);
    // 7. MLP layers
    mgemm<0, true, true ><<<dim3(196, 2), 256>>>(fc_w0, p_X0, p_X1, nullptr, fc_b0,
                                                 nullptr, nullptr, 256, FCIN, NCOL, FCIN, FCIN);
    mgemm<0, true, true ><<<dim3(196, 2), 256>>>(fc_w1, p_X1, p_X0, nullptr, fc_b1,
                                                 nullptr, nullptr, 256, FCIN, NCOL, FCIN, FCIN);
    mgemm<0, true, true ><<<dim3(196, 2), 256>>>(fc_w2, p_X0, p_X1, nullptr, fc_b2,
                                                 nullptr, nullptr, 256, FCIN, NCOL, FCIN, FCIN);
    // 8. point logits
    mgemm<0, true, false><<<dim3(196, 2), 256>>>(w_log, p_X1, p_P, nullptr, b_log,
                                                 nullptr, nullptr, 256, FCIN, NCOL, FCIN, CCH);
    // 9. fused = relu(W_fuse @ refined + b); refine folded into B row select
    mgemm<3, false, true><<<dim3(784, 2), 256>>>(w_fuse, p_Ft, p_F, nullptr, b_fuse,
                                                 p_P, p_map, 256, 256, NPIX, 0, NPIX);
    // 10. x2 bilinear upsample + relu
    upsample_k<<<NB*CCH, 256>>>(out);
}